// round 14
// baseline (speedup 1.0000x reference)
#include <cuda_runtime.h>

#define T_DATA 20000
#define TOFF   256
#define NXI    20400   // g_INT2 rows: TOFF + 20000 + pad (pad read only for discarded outputs)
#define TILE   136     // k34 outputs per block; 148*136 = 20128 >= 20000
#define RPB    68      // k1f rows per block; 296*68 = 20128 >= 20000
#define NRB    296     // k1f row blocks (2 clean waves of 148)

// ---------------- device scratch ----------------
__device__ float2   g_INT2[NXI * 12];    // [x][s] = (IN_e, IN_i), x = TOFF + t
__device__ float4   g_KER4[12 * 200];    // (kes, kis, ken, kin) per (s,k)

__device__ __forceinline__ float sigmoidf_(float x) {
    return 1.0f / (1.0f + __expf(-x));
}

// packed f32x2 helpers (Blackwell)
#define FMA2(acc, a, b) \
    asm("fma.rn.f32x2 %0, %1, %2, %3;" : "=l"(acc) : "l"(a), "l"(b), "l"(acc))
#define PACK2(out, lo, hi) \
    asm("mov.b64 %0, {%1, %2};" : "=l"(out) : "f"(lo), "f"(hi))
#define UNPACK2(lo, hi, in) \
    asm("mov.b64 {%0, %1}, %2;" : "=f"(lo), "=f"(hi) : "l"(in))

__device__ __forceinline__ float coef1(const float* __restrict__ W,
                                       const float* __restrict__ D,
                                       int s, int c, float t) {
    float ts = fmaxf(t - expf(D[s * 2 + c]), 0.f);
    float acc = 0.f;
    #pragma unroll
    for (int b = 0; b < 3; ++b) {
        float tau = expf(0.5f * (float)b);
        float tt  = ts / tau;
        acc += W[s * 6 + b * 2 + c] * tt * expf(-tt);
    }
    return acc;
}

// ---------------- K1f: per-block tables + pack + popcount GEMM --------------
// Row blocks [0, NRB): build the permuted C bitmasks in smem via ballots
// (120 KB re-read per block, L2-resident), then pack+popc 68 rows each with a
// depth-8 prefetch ring. Side blocks NRB / NRB+1: g_KER4 and the t<0 pad.
__global__ void __launch_bounds__(512, 2)
k1f(const float4* __restrict__ Se4, const float4* __restrict__ Si4,
    const float4* __restrict__ Ce4, const float4* __restrict__ Ci4,
    const float* __restrict__ Wss,  const float* __restrict__ Wns,
    const float* __restrict__ Dss,  const float* __restrict__ Dns) {
    int tid  = threadIdx.x;
    int bid  = blockIdx.x;
    const float4 z4 = make_float4(0.f, 0.f, 0.f, 0.f);

    if (bid >= NRB) {
        if (bid == NRB) {                              // synaptic kernel coefficients
            for (int gid = tid; gid < 2400; gid += 512) {
                int s = gid / 200, k = gid % 200;
                float t = (float)k;
                float4 o;
                o.x = coef1(Wss, Dss, s, 0, t);
                o.y = coef1(Wss, Dss, s, 1, t);
                o.z = coef1(Wns, Dns, s, 0, t);
                o.w = coef1(Wns, Dns, s, 1, t);
                g_KER4[gid] = o;
            }
        } else {                                       // zero t<0 pad of g_INT2
            for (int i = tid; i < TOFF * 12; i += 512)
                g_INT2[i] = make_float2(0.f, 0.f);
        }
        return;
    }

    __shared__ unsigned sCE[768], sCI[192];
    int warp = tid >> 5, lane = tid & 31;

    // ---- per-block mask tables: bit l of word (4w+c, s) = C[s][128w+4l+c] ----
    #pragma unroll
    for (int gw = warp; gw < 240; gw += 16) {
        if (gw < 192) {                                // E: 16 chunks x 12 subunits
            int w = gw / 12, s = gw % 12;
            int f = w * 32 + lane;
            float4 v = (f < 500) ? __ldg(Ce4 + s * 500 + f) : z4;
            unsigned m0 = __ballot_sync(0xffffffffu, v.x != 0.f);
            unsigned m1 = __ballot_sync(0xffffffffu, v.y != 0.f);
            unsigned m2 = __ballot_sync(0xffffffffu, v.z != 0.f);
            unsigned m3 = __ballot_sync(0xffffffffu, v.w != 0.f);
            if (lane == 0) {
                sCE[(4 * w + 0) * 12 + s] = m0;
                sCE[(4 * w + 1) * 12 + s] = m1;
                sCE[(4 * w + 2) * 12 + s] = m2;
                sCE[(4 * w + 3) * 12 + s] = m3;
            }
        } else {                                       // I: 4 chunks x 12 subunits
            int j = gw - 192;
            int w = j / 12, s = j % 12;
            int f = w * 32 + lane;
            float4 v = (f < 125) ? __ldg(Ci4 + s * 125 + f) : z4;
            unsigned m0 = __ballot_sync(0xffffffffu, v.x != 0.f);
            unsigned m1 = __ballot_sync(0xffffffffu, v.y != 0.f);
            unsigned m2 = __ballot_sync(0xffffffffu, v.z != 0.f);
            unsigned m3 = __ballot_sync(0xffffffffu, v.w != 0.f);
            if (lane == 0) {
                sCI[(4 * w + 0) * 12 + s] = m0;
                sCI[(4 * w + 1) * 12 + s] = m1;
                sCI[(4 * w + 2) * 12 + s] = m2;
                sCI[(4 * w + 3) * 12 + s] = m3;
            }
        }
    }
    __syncthreads();

    // ---- pack + popcount for rows [bid*RPB, bid*RPB + RPB) ----
    int lc = (lane < 12) ? lane : 0;
    int rowbase = bid * RPB;
    for (int r = warp; r < RPB; r += 16) {             // warp-uniform row
        int row = rowbase + r;
        if (row >= T_DATA) break;
        const float4* rE = Se4 + (size_t)row * 500;
        const float4* rI = Si4 + (size_t)row * 125;
        int accE = 0, accI = 0;
        float4 vb[8];
        #pragma unroll
        for (int j = 0; j < 8; ++j) {
            int f = j * 32 + lane;
            vb[j] = (f < 500) ? __ldg(rE + f) : z4;
        }
        #pragma unroll
        for (int w = 0; w < 20; ++w) {
            float4 v = vb[w & 7];
            int wn = w + 8;
            if (wn < 16) {
                int f = wn * 32 + lane;
                vb[w & 7] = (f < 500) ? __ldg(rE + f) : z4;
            } else if (wn < 20) {
                int f = (wn - 16) * 32 + lane;
                vb[w & 7] = (f < 125) ? __ldg(rI + f) : z4;
            }
            unsigned m0 = __ballot_sync(0xffffffffu, v.x != 0.f);
            unsigned m1 = __ballot_sync(0xffffffffu, v.y != 0.f);
            unsigned m2 = __ballot_sync(0xffffffffu, v.z != 0.f);
            unsigned m3 = __ballot_sync(0xffffffffu, v.w != 0.f);
            if (w < 16) {
                int bb = w * 48 + lc;
                accE += __popc(m0 & sCE[bb]);
                accE += __popc(m1 & sCE[bb + 12]);
                accE += __popc(m2 & sCE[bb + 24]);
                accE += __popc(m3 & sCE[bb + 36]);
            } else {
                int bb = (w - 16) * 48 + lc;
                accI += __popc(m0 & sCI[bb]);
                accI += __popc(m1 & sCI[bb + 12]);
                accI += __popc(m2 & sCI[bb + 24]);
                accI += __popc(m3 & sCI[bb + 36]);
            }
        }
        if (lane < 12)
            g_INT2[(TOFF + row) * 12 + lane] =
                make_float2((float)accE, (float)accI);
    }
}

// ---------------- K34: fused conv + cascade (round-9 proven body) -----------
#define SS_OFF   0        // float [12*148] syn_s
#define SNS_OFF  1776     // float [12*148] syn_ns
#define XNO_OFF  3552     // float [12*148] cascade levels
#define SOUT_OFF 5328     // float [136*35]
#define BUFSZ    10088    // sIN (348*12 float2 = 8352 floats) aliases offset 0

__global__ void __launch_bounds__(384) k34(const float* __restrict__ Cden,
                                           const float* __restrict__ Ths,
                                           const float* __restrict__ Thns,
                                           const float* __restrict__ Wssub,
                                           const float* __restrict__ Wnssub,
                                           float* __restrict__ out) {
    __shared__ __align__(16) float buf[BUFSZ];
    __shared__ float cwns[144], cds[144];
    __shared__ float ths[12], thns[12], ws[12], wns[12];
    int tid = threadIdx.x;
    int t0  = blockIdx.x * TILE;

    if (tid < 144) {
        float c = Cden[tid];
        cds [tid] = c;
        cwns[tid] = c * Wnssub[tid % 12];
    }
    if (tid >= 160 && tid < 172) {
        int q = tid - 160;
        ths [q] = Ths[q];
        thns[q] = Thns[q];
        ws  [q] = Wssub[q];
        wns [q] = Wnssub[q];
    }

    // stage IN window: sIN[s][xx] = IN at t = t0 - 212 + xx, xx in [0,348)
    float2* sIN = (float2*)buf;                        // [s][xx], pitch 348
    {
        int base = (TOFF + t0 - 212) * 12;
        for (int i = tid; i < 4176; i += 384) {
            int xx = i / 12, s = i % 12;
            sIN[s * 348 + xx] = g_INT2[base + i];
        }
    }
    __syncthreads();

    // conv: warp = subunit, lane owns 5 adjacent outputs, sliding reg window
    int warp = tid >> 5, lane = tid & 31;
    int s = warp;
    int mbase = 5 * lane;
    const unsigned long long* row =
        (const unsigned long long*)(sIN + s * 348);
    unsigned long long W0, W1, W2, W3, W4;
    unsigned long long aS0 = 0, aS1 = 0, aS2 = 0, aS3 = 0, aS4 = 0;
    unsigned long long aN0 = 0, aN1 = 0, aN2 = 0, aN3 = 0, aN4 = 0;
    W0 = row[min(mbase + 200, 347)];
    W1 = row[min(mbase + 201, 347)];
    W2 = row[min(mbase + 202, 347)];
    W3 = row[min(mbase + 203, 347)];
    W4 = row[min(mbase + 204, 347)];
    const float4* kp = g_KER4 + s * 200;
    #pragma unroll 5
    for (int k = 0; k < 200; ++k) {
        float4 kc = __ldg(kp + k);
        unsigned long long cs, cn;
        PACK2(cs, kc.x, kc.y);
        PACK2(cn, kc.z, kc.w);
        FMA2(aS0, W0, cs); FMA2(aN0, W0, cn);
        FMA2(aS1, W1, cs); FMA2(aN1, W1, cn);
        FMA2(aS2, W2, cs); FMA2(aN2, W2, cn);
        FMA2(aS3, W3, cs); FMA2(aN3, W3, cn);
        FMA2(aS4, W4, cs); FMA2(aN4, W4, cn);
        W4 = W3; W3 = W2; W2 = W1; W1 = W0;
        W0 = row[min(mbase + 199 - k, 347)];
    }
    __syncthreads();                                   // sIN dead; buf reusable
    {
        float lo, hi;
        #pragma unroll
        for (int j = 0; j < 5; ++j) {
            int m = mbase + j;
            if (m < 148) {
                unsigned long long vS, vN;
                switch (j) {
                    case 0: vS = aS0; vN = aN0; break;
                    case 1: vS = aS1; vN = aN1; break;
                    case 2: vS = aS2; vN = aN2; break;
                    case 3: vS = aS3; vN = aN3; break;
                    default: vS = aS4; vN = aN4; break;
                }
                UNPACK2(lo, hi, vS); buf[SS_OFF  + s * 148 + m] = lo + hi;
                UNPACK2(lo, hi, vN); buf[SNS_OFF + s * 148 + m] = lo + hi;
            }
        }
    }
    __syncthreads();

    // cascade: 12 lower-triangular levels over cols m = 0..147
    #pragma unroll
    for (int i = 0; i < 12; ++i) {
        if (tid < 148) {
            int t = t0 - 12 + tid;
            float v = 0.f;
            if (t >= 0) {
                float x = buf[SNS_OFF + i * 148 + tid] + thns[i];
                #pragma unroll
                for (int j = 0; j < i; ++j) {
                    float yp = (tid > 0) ? buf[XNO_OFF + j * 148 + tid - 1] : 0.f;
                    x = fmaf(cwns[i * 12 + j], yp, x);
                }
                v = sigmoidf_(x);
            }
            buf[XNO_OFF + i * 148 + tid] = v;
        }
        __syncthreads();
    }

    // epilogue: per-t outputs
    if (tid < TILE) {
        int t = t0 + tid, h = tid + 12;
        if (t < T_DATA) {
            float ysp[12];
            if (t == 0) {
                #pragma unroll
                for (int j = 0; j < 12; ++j) ysp[j] = 0.f;
            } else {
                float x0 = buf[SS_OFF + 0 * 148 + tid + 11] + ths[0];
                ysp[0] = sigmoidf_(x0) * ws[0];
                #pragma unroll
                for (int j = 1; j < 12; ++j)
                    ysp[j] = buf[XNO_OFF + j * 148 + h - 1] * ws[j];
            }
            float* o = buf + SOUT_OFF + tid * 35;
            #pragma unroll
            for (int i = 0; i < 12; ++i) {
                float xs = buf[SS_OFF + i * 148 + tid + 12] + ths[i];
                #pragma unroll
                for (int j = 0; j < i; ++j) xs = fmaf(cds[i * 12 + j], ysp[j], xs);
                float sg  = sigmoidf_(xs);
                float xti = buf[XNO_OFF + i * 148 + h];
                o[i]      = (i == 0) ? sg * ws[0] : xti * ws[i];
                o[12 + i] = xti * wns[i];
                if (i >= 1) o[24 + i - 1] = sg;
            }
        }
    }
    __syncthreads();
    int nvalid = T_DATA - t0; if (nvalid > TILE) nvalid = TILE;
    float* ob = out + (size_t)t0 * 35;
    if (nvalid == TILE) {
        float4* o4 = (float4*)ob;                      // t0*35 % 4 == 0
        const float4* sb = (const float4*)(buf + SOUT_OFF);
        for (int i = tid; i < 1190; i += 384) o4[i] = sb[i];
    } else if (nvalid > 0) {
        int nf = nvalid * 35;
        for (int i = tid; i < nf; i += 384) ob[i] = buf[SOUT_OFF + i];
    }
}

// ---------------- launch ----------------
extern "C" void kernel_launch(void* const* d_in, const int* in_sizes, int n_in,
                              void* d_out, int out_size) {
    const float* S_e      = (const float*)d_in[0];
    const float* S_i      = (const float*)d_in[1];
    const float* C_syn_e  = (const float*)d_in[2];
    const float* C_syn_i  = (const float*)d_in[3];
    const float* C_den    = (const float*)d_in[4];
    const float* W_s_syn  = (const float*)d_in[5];
    const float* W_ns_syn = (const float*)d_in[6];
    const float* D_s      = (const float*)d_in[7];
    const float* D_ns     = (const float*)d_in[8];
    const float* Theta_s  = (const float*)d_in[9];
    const float* Theta_ns = (const float*)d_in[10];
    const float* W_s_sub  = (const float*)d_in[11];
    const float* W_ns_sub = (const float*)d_in[12];
    float* out = (float*)d_out;

    k1f<<<NRB + 2, 512>>>((const float4*)S_e, (const float4*)S_i,
                          (const float4*)C_syn_e, (const float4*)C_syn_i,
                          W_s_syn, W_ns_syn, D_s, D_ns);
    k34<<<148, 384>>>(C_den, Theta_s, Theta_ns, W_s_sub, W_ns_sub, out);
}

// round 16
// speedup vs baseline: 1.0903x; 1.0903x over previous
#include <cuda_runtime.h>

#define T_DATA 20000
#define TOFF   256
#define NXI    20400   // g_INT2 rows: TOFF + 20000 + pad (pad read only for discarded outputs)
#define TILE   136     // k34 outputs per block; 148*136 = 20128 >= 20000

// ---------------- device scratch ----------------
__device__ float2   g_INT2[NXI * 12];    // [x][s] = (IN_e, IN_i), x = TOFF + t
__device__ float4   g_KER4[12 * 200];    // (kes, kis, ken, kin) per (s,k)
__device__ unsigned g_CTBE[64 * 12];     // permuted bit layout (matches k1f ballots)
__device__ unsigned g_CTBI[16 * 12];

__device__ __forceinline__ float sigmoidf_(float x) {
    return 1.0f / (1.0f + __expf(-x));
}

// packed f32x2 helpers (Blackwell)
#define FMA2(acc, a, b) \
    asm("fma.rn.f32x2 %0, %1, %2, %3;" : "=l"(acc) : "l"(a), "l"(b), "l"(acc))
#define PACK2(out, lo, hi) \
    asm("mov.b64 %0, {%1, %2};" : "=l"(out) : "f"(lo), "f"(hi))
#define UNPACK2(lo, hi, in) \
    asm("mov.b64 {%0, %1}, %2;" : "=f"(lo), "=f"(hi) : "l"(in))

// ---------------- K0a: pack C_syn via coalesced float4 + ballots (round-9) ----
__global__ void __launch_bounds__(960) k0a(const float4* __restrict__ Ce4,
                                           const float4* __restrict__ Ci4) {
    int warp = threadIdx.x >> 5, lane = threadIdx.x & 31;
    int gw = blockIdx.x * 30 + warp;                 // 0..239
    if (gw < 192) {                                   // E: 16 chunks x 12 subunits
        int w = gw / 12, s = gw % 12;
        int f = w * 32 + lane;
        float4 v = (f < 500) ? __ldg(Ce4 + s * 500 + f)
                             : make_float4(0.f, 0.f, 0.f, 0.f);
        unsigned m0 = __ballot_sync(0xffffffffu, v.x != 0.f);
        unsigned m1 = __ballot_sync(0xffffffffu, v.y != 0.f);
        unsigned m2 = __ballot_sync(0xffffffffu, v.z != 0.f);
        unsigned m3 = __ballot_sync(0xffffffffu, v.w != 0.f);
        if (lane == 0) {
            g_CTBE[(4 * w + 0) * 12 + s] = m0;
            g_CTBE[(4 * w + 1) * 12 + s] = m1;
            g_CTBE[(4 * w + 2) * 12 + s] = m2;
            g_CTBE[(4 * w + 3) * 12 + s] = m3;
        }
    } else if (gw < 240) {                            // I: 4 chunks x 12 subunits
        int j = gw - 192;
        int w = j / 12, s = j % 12;
        int f = w * 32 + lane;
        float4 v = (f < 125) ? __ldg(Ci4 + s * 125 + f)
                             : make_float4(0.f, 0.f, 0.f, 0.f);
        unsigned m0 = __ballot_sync(0xffffffffu, v.x != 0.f);
        unsigned m1 = __ballot_sync(0xffffffffu, v.y != 0.f);
        unsigned m2 = __ballot_sync(0xffffffffu, v.z != 0.f);
        unsigned m3 = __ballot_sync(0xffffffffu, v.w != 0.f);
        if (lane == 0) {
            g_CTBI[(4 * w + 0) * 12 + s] = m0;
            g_CTBI[(4 * w + 1) * 12 + s] = m1;
            g_CTBI[(4 * w + 2) * 12 + s] = m2;
            g_CTBI[(4 * w + 3) * 12 + s] = m3;
        }
    }
}

__device__ __forceinline__ float coef1(const float* __restrict__ W,
                                       const float* __restrict__ D,
                                       int s, int c, float t) {
    float ts = fmaxf(t - expf(D[s * 2 + c]), 0.f);
    float acc = 0.f;
    #pragma unroll
    for (int b = 0; b < 3; ++b) {
        float tau = expf(0.5f * (float)b);
        float tt  = ts / tau;
        acc += W[s * 6 + b * 2 + c] * tt * expf(-tt);
    }
    return acc;
}

// ---------------- K1f: fused bit-pack + popcount GEMM (round-9 proven) -------
__global__ void __launch_bounds__(256) k1f(const float4* __restrict__ Se4,
                                           const float4* __restrict__ Si4,
                                           const float* __restrict__ Wss,
                                           const float* __restrict__ Wns,
                                           const float* __restrict__ Dss,
                                           const float* __restrict__ Dns) {
    if (blockIdx.x >= 2500) {
        int gid = (blockIdx.x - 2500) * 256 + threadIdx.x;
        if (gid < 2400) {
            int s = gid / 200, k = gid % 200;
            float t = (float)k;
            float4 o;
            o.x = coef1(Wss, Dss, s, 0, t);
            o.y = coef1(Wss, Dss, s, 1, t);
            o.z = coef1(Wns, Dns, s, 0, t);
            o.w = coef1(Wns, Dns, s, 1, t);
            g_KER4[gid] = o;
        } else if (gid < 5472) {
            g_INT2[gid - 2400] = make_float2(0.f, 0.f);   // zero pad x < 256
        }
        return;
    }
    __shared__ unsigned sCE[768], sCI[192];
    int tid = threadIdx.x;
    for (int i = tid; i < 768; i += 256) sCE[i] = g_CTBE[i];
    if (tid < 192) sCI[tid] = g_CTBI[tid];
    __syncthreads();

    int lane = tid & 31;
    int row  = blockIdx.x * 8 + (tid >> 5);
    const float4* rE = Se4 + (size_t)row * 500;
    const float4* rI = Si4 + (size_t)row * 125;
    int lc = (lane < 12) ? lane : 0;
    int accE = 0, accI = 0;
    const float4 z4 = make_float4(0.f, 0.f, 0.f, 0.f);

    float4 vb[4];
    #pragma unroll
    for (int j = 0; j < 4; ++j) vb[j] = __ldg(rE + j * 32 + lane);

    #pragma unroll
    for (int w = 0; w < 16; ++w) {
        float4 v = vb[w & 3];
        int wn = w + 4;
        if (wn < 16) {
            int f = wn * 32 + lane;
            vb[w & 3] = (f < 500) ? __ldg(rE + f) : z4;
        } else {
            int f = (wn - 16) * 32 + lane;
            vb[w & 3] = (f < 125) ? __ldg(rI + f) : z4;
        }
        unsigned m0 = __ballot_sync(0xffffffffu, v.x != 0.f);
        unsigned m1 = __ballot_sync(0xffffffffu, v.y != 0.f);
        unsigned m2 = __ballot_sync(0xffffffffu, v.z != 0.f);
        unsigned m3 = __ballot_sync(0xffffffffu, v.w != 0.f);
        int b = w * 48 + lc;
        accE += __popc(m0 & sCE[b]);
        accE += __popc(m1 & sCE[b + 12]);
        accE += __popc(m2 & sCE[b + 24]);
        accE += __popc(m3 & sCE[b + 36]);
    }
    #pragma unroll
    for (int w = 0; w < 4; ++w) {
        float4 v = vb[w];
        unsigned m0 = __ballot_sync(0xffffffffu, v.x != 0.f);
        unsigned m1 = __ballot_sync(0xffffffffu, v.y != 0.f);
        unsigned m2 = __ballot_sync(0xffffffffu, v.z != 0.f);
        unsigned m3 = __ballot_sync(0xffffffffu, v.w != 0.f);
        int b = w * 48 + lc;
        accI += __popc(m0 & sCI[b]);
        accI += __popc(m1 & sCI[b + 12]);
        accI += __popc(m2 & sCI[b + 24]);
        accI += __popc(m3 & sCI[b + 36]);
    }
    if (lane < 12)
        g_INT2[(TOFF + row) * 12 + lane] = make_float2((float)accE, (float)accI);
}

// ---------------- K34 v3: tap-split conv (24 warps) + cascade ---------------
// 148 blocks x 136 t, 768 threads. warp = (half, s): each warp convolves 100
// taps for subunit s over 148 outputs (5/lane, sliding reg window, f32x2).
// Halves combined via smem partials aliased into the dead XNO/SOUT region.
#define SS_OFF   0        // float [12*148] syn_s
#define SNS_OFF  1776     // float [12*148] syn_ns
#define XNO_OFF  3552     // float [12*148] cascade levels
#define SOUT_OFF 5328     // float [136*35]
#define PART_OFF 3552     // float2 [12*148] half-1 partials (dead before XNO use)
#define BUFSZ    10088    // sIN (348*12 float2 = 8352 floats) aliases offset 0

__global__ void __launch_bounds__(768) k34(const float* __restrict__ Cden,
                                           const float* __restrict__ Ths,
                                           const float* __restrict__ Thns,
                                           const float* __restrict__ Wssub,
                                           const float* __restrict__ Wnssub,
                                           float* __restrict__ out) {
    __shared__ __align__(16) float buf[BUFSZ];
    __shared__ float cwns[144], cds[144];
    __shared__ float ths[12], thns[12], ws[12], wns[12];
    int tid = threadIdx.x;
    int t0  = blockIdx.x * TILE;

    if (tid < 144) {
        float c = Cden[tid];
        cds [tid] = c;
        cwns[tid] = c * Wnssub[tid % 12];
    }
    if (tid >= 160 && tid < 172) {
        int q = tid - 160;
        ths [q] = Ths[q];
        thns[q] = Thns[q];
        ws  [q] = Wssub[q];
        wns [q] = Wnssub[q];
    }

    // stage IN window: sIN[s][xx] = IN at t = t0 - 212 + xx, xx in [0,348)
    float2* sIN = (float2*)buf;                        // [s][xx], pitch 348
    {
        int base = (TOFF + t0 - 212) * 12;
        for (int i = tid; i < 4176; i += 768) {
            int xx = i / 12, s = i % 12;
            sIN[s * 348 + xx] = g_INT2[base + i];
        }
    }
    __syncthreads();

    // conv: warp = (half, s); half h covers taps k = 100h .. 100h+99.
    // Output m needs xx = m + 200 - k; window regs W_j slide downward.
    int warp = tid >> 5, lane = tid & 31;
    int s = warp % 12, half = warp / 12;
    int mbase = 5 * lane;
    const unsigned long long* row =
        (const unsigned long long*)(sIN + s * 348);
    int base0 = mbase + 200 - 100 * half;              // init window index (j=0)
    unsigned long long W0, W1, W2, W3, W4;
    unsigned long long aS0 = 0, aS1 = 0, aS2 = 0, aS3 = 0, aS4 = 0;
    unsigned long long aN0 = 0, aN1 = 0, aN2 = 0, aN3 = 0, aN4 = 0;
    W0 = row[min(base0 + 0, 347)];
    W1 = row[min(base0 + 1, 347)];
    W2 = row[min(base0 + 2, 347)];
    W3 = row[min(base0 + 3, 347)];
    W4 = row[min(base0 + 4, 347)];
    const float4* kp = g_KER4 + s * 200 + 100 * half;
    #pragma unroll 5
    for (int kk = 0; kk < 100; ++kk) {
        float4 kc = __ldg(kp + kk);
        unsigned long long cs, cn;
        PACK2(cs, kc.x, kc.y);
        PACK2(cn, kc.z, kc.w);
        FMA2(aS0, W0, cs); FMA2(aN0, W0, cn);
        FMA2(aS1, W1, cs); FMA2(aN1, W1, cn);
        FMA2(aS2, W2, cs); FMA2(aN2, W2, cn);
        FMA2(aS3, W3, cs); FMA2(aN3, W3, cn);
        FMA2(aS4, W4, cs); FMA2(aN4, W4, cn);
        W4 = W3; W3 = W2; W2 = W1; W1 = W0;
        W0 = row[max(base0 - 1 - kk, 0)];              // next incoming (index >= 0)
    }
    __syncthreads();                                   // sIN dead; buf reusable

    // half 1 publishes partial (vs, vn) per output; half 0 combines.
    float2* sPart = (float2*)(buf + PART_OFF);         // [s*148 + m]
    {
        float lo, hi;
        if (half == 1) {
            #pragma unroll
            for (int j = 0; j < 5; ++j) {
                int m = mbase + j;
                if (m < 148) {
                    unsigned long long vS, vN;
                    switch (j) {
                        case 0: vS = aS0; vN = aN0; break;
                        case 1: vS = aS1; vN = aN1; break;
                        case 2: vS = aS2; vN = aN2; break;
                        case 3: vS = aS3; vN = aN3; break;
                        default: vS = aS4; vN = aN4; break;
                    }
                    float vs, vn;
                    UNPACK2(lo, hi, vS); vs = lo + hi;
                    UNPACK2(lo, hi, vN); vn = lo + hi;
                    sPart[s * 148 + m] = make_float2(vs, vn);
                }
            }
        }
    }
    __syncthreads();
    if (half == 0) {
        float lo, hi;
        #pragma unroll
        for (int j = 0; j < 5; ++j) {
            int m = mbase + j;
            if (m < 148) {
                unsigned long long vS, vN;
                switch (j) {
                    case 0: vS = aS0; vN = aN0; break;
                    case 1: vS = aS1; vN = aN1; break;
                    case 2: vS = aS2; vN = aN2; break;
                    case 3: vS = aS3; vN = aN3; break;
                    default: vS = aS4; vN = aN4; break;
                }
                float2 p = sPart[s * 148 + m];
                UNPACK2(lo, hi, vS); buf[SS_OFF  + s * 148 + m] = lo + hi + p.x;
                UNPACK2(lo, hi, vN); buf[SNS_OFF + s * 148 + m] = lo + hi + p.y;
            }
        }
    }
    __syncthreads();

    // cascade: 12 lower-triangular levels over cols m = 0..147 (XNO overwrites
    // the now-dead sPart region)
    #pragma unroll
    for (int i = 0; i < 12; ++i) {
        if (tid < 148) {
            int t = t0 - 12 + tid;
            float v = 0.f;
            if (t >= 0) {
                float x = buf[SNS_OFF + i * 148 + tid] + thns[i];
                #pragma unroll
                for (int j = 0; j < i; ++j) {
                    float yp = (tid > 0) ? buf[XNO_OFF + j * 148 + tid - 1] : 0.f;
                    x = fmaf(cwns[i * 12 + j], yp, x);
                }
                v = sigmoidf_(x);
            }
            buf[XNO_OFF + i * 148 + tid] = v;
        }
        __syncthreads();
    }

    // epilogue: per-t outputs
    if (tid < TILE) {
        int t = t0 + tid, h = tid + 12;
        if (t < T_DATA) {
            float ysp[12];
            if (t == 0) {
                #pragma unroll
                for (int j = 0; j < 12; ++j) ysp[j] = 0.f;
            } else {
                float x0 = buf[SS_OFF + 0 * 148 + tid + 11] + ths[0];
                ysp[0] = sigmoidf_(x0) * ws[0];
                #pragma unroll
                for (int j = 1; j < 12; ++j)
                    ysp[j] = buf[XNO_OFF + j * 148 + h - 1] * ws[j];
            }
            float* o = buf + SOUT_OFF + tid * 35;
            #pragma unroll
            for (int i = 0; i < 12; ++i) {
                float xs = buf[SS_OFF + i * 148 + tid + 12] + ths[i];
                #pragma unroll
                for (int j = 0; j < i; ++j) xs = fmaf(cds[i * 12 + j], ysp[j], xs);
                float sg  = sigmoidf_(xs);
                float xti = buf[XNO_OFF + i * 148 + h];
                o[i]      = (i == 0) ? sg * ws[0] : xti * ws[i];
                o[12 + i] = xti * wns[i];
                if (i >= 1) o[24 + i - 1] = sg;
            }
        }
    }
    __syncthreads();
    int nvalid = T_DATA - t0; if (nvalid > TILE) nvalid = TILE;
    float* ob = out + (size_t)t0 * 35;
    if (nvalid == TILE) {
        float4* o4 = (float4*)ob;                      // t0*35 % 4 == 0
        const float4* sb = (const float4*)(buf + SOUT_OFF);
        for (int i = tid; i < 1190; i += 768) o4[i] = sb[i];
    } else if (nvalid > 0) {
        int nf = nvalid * 35;
        for (int i = tid; i < nf; i += 768) ob[i] = buf[SOUT_OFF + i];
    }
}

// ---------------- launch ----------------
extern "C" void kernel_launch(void* const* d_in, const int* in_sizes, int n_in,
                              void* d_out, int out_size) {
    const float* S_e      = (const float*)d_in[0];
    const float* S_i      = (const float*)d_in[1];
    const float* C_syn_e  = (const float*)d_in[2];
    const float* C_syn_i  = (const float*)d_in[3];
    const float* C_den    = (const float*)d_in[4];
    const float* W_s_syn  = (const float*)d_in[5];
    const float* W_ns_syn = (const float*)d_in[6];
    const float* D_s      = (const float*)d_in[7];
    const float* D_ns     = (const float*)d_in[8];
    const float* Theta_s  = (const float*)d_in[9];
    const float* Theta_ns = (const float*)d_in[10];
    const float* W_s_sub  = (const float*)d_in[11];
    const float* W_ns_sub = (const float*)d_in[12];
    float* out = (float*)d_out;

    k0a<<<8, 960>>>((const float4*)C_syn_e, (const float4*)C_syn_i);
    k1f<<<2522, 256>>>((const float4*)S_e, (const float4*)S_i,
                       W_s_syn, W_ns_syn, D_s, D_ns);
    k34<<<148, 768>>>(C_den, Theta_s, Theta_ns, W_s_sub, W_ns_sub, out);
}